// round 7
// baseline (speedup 1.0000x reference)
#include <cuda_runtime.h>

#define NSTATE (1u << 22)

// swizzles on float4-unit indices (permute within 128B rows, keep 16B align)
__device__ __forceinline__ int SWA(int u) { return u ^ ((u >> 3) & 7); }
__device__ __forceinline__ int SWB(int u) { return u ^ ((u >> 4) & 7); }

// one 2x2 rotation butterfly: new = (c*I - i*s*X) * old
__device__ __forceinline__ void gate1(float& r0, float& i0, float& r1, float& i1,
                                      float c, float s)
{
    float nr0 = c * r0 + s * i1;
    float ni0 = c * i0 - s * r1;
    float nr1 = c * r1 + s * i0;
    float ni1 = c * i1 - s * r0;
    r0 = nr0; i0 = ni0; r1 = nr1; i1 = ni1;
}

// gate on a pair of interleaved units (each unit = 2 complex: r0,i0,r1,i1)
__device__ __forceinline__ void gateU(float4& A, float4& B, float c, float s)
{
    gate1(A.x, A.y, B.x, B.y, c, s);
    gate1(A.z, A.w, B.z, B.w, c, s);
}

// gate across two (R,I) float4 pairs, componentwise (4 complex each side)
__device__ __forceinline__ void gateV(float4& Ra, float4& Ia, float4& Rb, float4& Ib,
                                      float c, float s)
{
    gate1(Ra.x, Ia.x, Rb.x, Ib.x, c, s);
    gate1(Ra.y, Ia.y, Rb.y, Ib.y, c, s);
    gate1(Ra.z, Ia.z, Rb.z, Ib.z, c, s);
    gate1(Ra.w, Ia.w, Rb.w, Ib.w, c, s);
}

// per-CTA coefficient table: sc[a]=cos(angle[a]/2), ss[a]=sin(angle[a]/2).
// Complex bit b uses angle index 21-b.
#define MAKE_COEFS(ang, sc, ss, t)                                            \
    do {                                                                      \
        if ((t) < 22) {                                                       \
            float c_, s_;                                                     \
            sincosf(0.5f * __ldg((ang) + (t)), &s_, &c_);                     \
            (sc)[t] = c_; (ss)[t] = s_;                                       \
        }                                                                     \
    } while (0)

// ---------------------------------------------------------------------------
// Kernel A: gates on complex bits 0..12 (angles 21..9).
// Tile = 8192 contiguous complex (64KB smem, 4096 units). 512 threads.
// Phases: fill(bits 0-3) ; bits 4-6 ; bits 7-9 ; drain(bits 10-12).
// ---------------------------------------------------------------------------
__global__ void __launch_bounds__(512, 2) gateA(const float* __restrict__ xr,
                                                const float* __restrict__ xi,
                                                const float* __restrict__ ang,
                                                float* __restrict__ outr,
                                                float* __restrict__ outi)
{
    extern __shared__ float4 sm[];            // 4096 units = 64KB
    __shared__ float sc[22], ss[22];
    const int t = threadIdx.x;
    const unsigned base = (unsigned)blockIdx.x << 13;

    MAKE_COEFS(ang, sc, ss, t);
    __syncthreads();

    // ---- fill: 16 contiguous complex/thread, gate bits 0..3 ----
    {
        float4 R[4], I[4];
        const float4* pr = reinterpret_cast<const float4*>(xr + base) + t * 4;
        const float4* pi = reinterpret_cast<const float4*>(xi + base) + t * 4;
#pragma unroll
        for (int q = 0; q < 4; ++q) { R[q] = pr[q]; I[q] = pi[q]; }

        float c0 = sc[21], s0 = ss[21], c1 = sc[20], s1 = ss[20];
        float c2 = sc[19], s2 = ss[19], c3 = sc[18], s3 = ss[18];
#pragma unroll
        for (int q = 0; q < 4; ++q) {         // bit 0
            gate1(R[q].x, I[q].x, R[q].y, I[q].y, c0, s0);
            gate1(R[q].z, I[q].z, R[q].w, I[q].w, c0, s0);
        }
#pragma unroll
        for (int q = 0; q < 4; ++q) {         // bit 1
            gate1(R[q].x, I[q].x, R[q].z, I[q].z, c1, s1);
            gate1(R[q].y, I[q].y, R[q].w, I[q].w, c1, s1);
        }
        gateV(R[0], I[0], R[1], I[1], c2, s2);   // bit 2
        gateV(R[2], I[2], R[3], I[3], c2, s2);
        gateV(R[0], I[0], R[2], I[2], c3, s3);   // bit 3
        gateV(R[1], I[1], R[3], I[3], c3, s3);

#pragma unroll
        for (int m = 0; m < 8; ++m) {
            int q = m >> 1;
            float4 u = (m & 1) ? make_float4(R[q].z, I[q].z, R[q].w, I[q].w)
                               : make_float4(R[q].x, I[q].x, R[q].y, I[q].y);
            sm[SWA(t * 8 + m)] = u;
        }
    }
    __syncthreads();

    float4 U[8];

    // ---- R2: gates bits 4-6 (unit bits 3-5), angles 17,16,15 ----
    {
        const int lo = t & 7, hi = t >> 3;
#pragma unroll
        for (int j = 0; j < 8; ++j) U[j] = sm[SWA((hi << 6) | (j << 3) | lo)];
        float c0 = sc[17], s0 = ss[17], c1 = sc[16], s1 = ss[16];
        float c2 = sc[15], s2 = ss[15];
#pragma unroll
        for (int p = 0; p < 8; ++p) if (!(p & 1)) gateU(U[p], U[p | 1], c0, s0);
#pragma unroll
        for (int p = 0; p < 8; ++p) if (!(p & 2)) gateU(U[p], U[p | 2], c1, s1);
#pragma unroll
        for (int p = 0; p < 8; ++p) if (!(p & 4)) gateU(U[p], U[p | 4], c2, s2);
#pragma unroll
        for (int j = 0; j < 8; ++j) sm[SWA((hi << 6) | (j << 3) | lo)] = U[j];
    }
    __syncthreads();

    // ---- R3: gates bits 7-9 (unit bits 6-8), angles 14,13,12 ----
    {
        const int lo = t & 63, hi = t >> 6;
#pragma unroll
        for (int j = 0; j < 8; ++j) U[j] = sm[SWA((hi << 9) | (j << 6) | lo)];
        float c0 = sc[14], s0 = ss[14], c1 = sc[13], s1 = ss[13];
        float c2 = sc[12], s2 = ss[12];
#pragma unroll
        for (int p = 0; p < 8; ++p) if (!(p & 1)) gateU(U[p], U[p | 1], c0, s0);
#pragma unroll
        for (int p = 0; p < 8; ++p) if (!(p & 2)) gateU(U[p], U[p | 2], c1, s1);
#pragma unroll
        for (int p = 0; p < 8; ++p) if (!(p & 4)) gateU(U[p], U[p | 4], c2, s2);
#pragma unroll
        for (int j = 0; j < 8; ++j) sm[SWA((hi << 9) | (j << 6) | lo)] = U[j];
    }
    __syncthreads();

    // ---- drain: gates bits 10-12 (unit bits 9-11), angles 11,10,9; store ----
    {
#pragma unroll
        for (int j = 0; j < 8; ++j) U[j] = sm[SWA((j << 9) | t)];
        float c0 = sc[11], s0 = ss[11], c1 = sc[10], s1 = ss[10];
        float c2 = sc[9],  s2 = ss[9];
#pragma unroll
        for (int p = 0; p < 8; ++p) if (!(p & 1)) gateU(U[p], U[p | 1], c0, s0);
#pragma unroll
        for (int p = 0; p < 8; ++p) if (!(p & 2)) gateU(U[p], U[p | 2], c1, s1);
#pragma unroll
        for (int p = 0; p < 8; ++p) if (!(p & 4)) gateU(U[p], U[p | 4], c2, s2);
#pragma unroll
        for (int j = 0; j < 8; ++j) {
            unsigned c = base + ((unsigned)j << 10) + 2u * (unsigned)t;
            float4 A = U[j];
            *reinterpret_cast<float2*>(outr + c) = make_float2(A.x, A.z);
            *reinterpret_cast<float2*>(outi + c) = make_float2(A.y, A.w);
        }
    }
}

// ---------------------------------------------------------------------------
// Kernel B: gates on complex bits 13..21 (angles 8..0). In-place on out.
// Tile = 8 contiguous (bits 0-2) x 512 strided h (bits 13-21) = 4096 complex.
// 256 threads, 32KB static smem (2048 units; unit u = (h<<2)|ul holds
// complex (h, lo=2ul..2ul+1) as r,i,r,i).
// Phases: fill+gates(h7,h8) ; h0-2 ; h3-5 ; drain+gate(h6).
// ---------------------------------------------------------------------------
__global__ void __launch_bounds__(256, 4) gateB(float* __restrict__ dr,
                                                float* __restrict__ di,
                                                const float* __restrict__ ang)
{
    __shared__ float4 sm[2048];               // 32KB
    __shared__ float sc[22], ss[22];
    const int t = threadIdx.x;
    const unsigned base = (unsigned)blockIdx.x << 3;   // k bits 3-12

    MAKE_COEFS(ang, sc, ss, t);
    __syncthreads();

    float4 U[8];

    // ---- fill + gates h7 (bit 20, angle 1), h8 (bit 21, angle 0) ----
    {
        const int uq = t & 1;                 // 16B half of 32B segment
        const int hm = t >> 1;                // h bits 0..6
#pragma unroll
        for (int j = 0; j < 4; ++j) {         // j = (h8<<1)|h7
            unsigned h = ((unsigned)j << 7) | (unsigned)hm;
            unsigned g = (h << 13) + base + 4u * (unsigned)uq;
            float4 R = *reinterpret_cast<const float4*>(dr + g);
            float4 I = *reinterpret_cast<const float4*>(di + g);
            U[2 * j]     = make_float4(R.x, I.x, R.y, I.y);
            U[2 * j + 1] = make_float4(R.z, I.z, R.w, I.w);
        }
        float c0 = sc[1], s0 = ss[1], c1 = sc[0], s1 = ss[0];
#pragma unroll
        for (int p = 0; p < 8; ++p) if (!(p & 2)) gateU(U[p], U[p | 2], c0, s0);
#pragma unroll
        for (int p = 0; p < 8; ++p) if (!(p & 4)) gateU(U[p], U[p | 4], c1, s1);
#pragma unroll
        for (int j = 0; j < 4; ++j)
#pragma unroll
            for (int ulo = 0; ulo < 2; ++ulo)
                sm[SWB((j << 9) | (hm << 2) | (uq << 1) | ulo)] = U[2 * j + ulo];
    }
    __syncthreads();

    // ---- Rd1: gates h0,h1,h2 (bits 13-15, angles 8,7,6) ----
    {
        const int ul = t & 3, hp = t >> 2;    // hp = h bits 3..8
#pragma unroll
        for (int j = 0; j < 8; ++j) U[j] = sm[SWB((hp << 5) | (j << 2) | ul)];
        float c0 = sc[8], s0 = ss[8], c1 = sc[7], s1 = ss[7];
        float c2 = sc[6], s2 = ss[6];
#pragma unroll
        for (int p = 0; p < 8; ++p) if (!(p & 1)) gateU(U[p], U[p | 1], c0, s0);
#pragma unroll
        for (int p = 0; p < 8; ++p) if (!(p & 2)) gateU(U[p], U[p | 2], c1, s1);
#pragma unroll
        for (int p = 0; p < 8; ++p) if (!(p & 4)) gateU(U[p], U[p | 4], c2, s2);
#pragma unroll
        for (int j = 0; j < 8; ++j) sm[SWB((hp << 5) | (j << 2) | ul)] = U[j];
    }
    __syncthreads();

    // ---- Rd2: gates h3,h4,h5 (bits 16-18, angles 5,4,3) ----
    {
        const int ul = t & 3, hl = (t >> 2) & 7, ht = t >> 5;  // ht = h bits 6-8
#pragma unroll
        for (int j = 0; j < 8; ++j)
            U[j] = sm[SWB((ht << 8) | (j << 5) | (hl << 2) | ul)];
        float c0 = sc[5], s0 = ss[5], c1 = sc[4], s1 = ss[4];
        float c2 = sc[3], s2 = ss[3];
#pragma unroll
        for (int p = 0; p < 8; ++p) if (!(p & 1)) gateU(U[p], U[p | 1], c0, s0);
#pragma unroll
        for (int p = 0; p < 8; ++p) if (!(p & 2)) gateU(U[p], U[p | 2], c1, s1);
#pragma unroll
        for (int p = 0; p < 8; ++p) if (!(p & 4)) gateU(U[p], U[p | 4], c2, s2);
#pragma unroll
        for (int j = 0; j < 8; ++j)
            sm[SWB((ht << 8) | (j << 5) | (hl << 2) | ul)] = U[j];
    }
    __syncthreads();

    // ---- drain: gate h6 (bit 19, angle 2); coalesced 32B-segment store ----
    {
        const int uq = t & 1;
        const int hlow = (t >> 1) & 63;       // h bits 0..5
        const int h8 = t >> 7;                // h bit 8
#pragma unroll
        for (int j = 0; j < 4; ++j) {         // j = (h7<<1)|h6
            int h = (h8 << 8) | (j << 6) | hlow;
#pragma unroll
            for (int ulo = 0; ulo < 2; ++ulo)
                U[2 * j + ulo] = sm[SWB((h << 2) | (uq << 1) | ulo)];
        }
        float c0 = sc[2], s0 = ss[2];
#pragma unroll
        for (int p = 0; p < 8; ++p) if (!(p & 2)) gateU(U[p], U[p | 2], c0, s0);
#pragma unroll
        for (int j = 0; j < 4; ++j) {
            unsigned h = ((unsigned)h8 << 8) | ((unsigned)j << 6) | (unsigned)hlow;
            unsigned g = (h << 13) + base + 4u * (unsigned)uq;
            float4 A = U[2 * j], B = U[2 * j + 1];
            *reinterpret_cast<float4*>(dr + g) = make_float4(A.x, A.z, B.x, B.z);
            *reinterpret_cast<float4*>(di + g) = make_float4(A.y, A.w, B.y, B.w);
        }
    }
}

extern "C" void kernel_launch(void* const* d_in, const int* in_sizes, int n_in,
                              void* d_out, int out_size)
{
    const float* xr  = (const float*)d_in[0];
    const float* xi  = (const float*)d_in[1];
    const float* ang = (const float*)d_in[2];
    float* outr = (float*)d_out;
    float* outi = outr + NSTATE;

    // Pass 1: gates on bits 0..12 (input -> out)
    const int shA = 4096 * sizeof(float4);    // 64KB
    cudaFuncSetAttribute(gateA, cudaFuncAttributeMaxDynamicSharedMemorySize, shA);
    gateA<<<NSTATE / 8192, 512, shA>>>(xr, xi, ang, outr, outi);

    // Pass 2: gates on bits 13..21 (in-place on out)
    gateB<<<NSTATE / 4096, 256>>>(outr, outi, ang);
}

// round 8
// speedup vs baseline: 1.1868x; 1.1868x over previous
#include <cuda_runtime.h>

#define NSTATE (1u << 22)

// swizzle on float4-unit index: bank-column = (u ^ (u>>3)) & 7
__device__ __forceinline__ int SW(int u) { return u ^ ((u >> 3) & 7); }

// half-CTA named barrier (ids 1,2; 256 threads each)
#define BAR_HALF(t) asm volatile("bar.sync %0, 256;" :: "r"(1 + ((t) >> 8)) : "memory")

// one 2x2 rotation butterfly: new = (c*I - i*s*X) * old
__device__ __forceinline__ void gate1(float& r0, float& i0, float& r1, float& i1,
                                      float c, float s)
{
    float nr0 = c * r0 + s * i1;
    float ni0 = c * i0 - s * r1;
    float nr1 = c * r1 + s * i0;
    float ni1 = c * i1 - s * r0;
    r0 = nr0; i0 = ni0; r1 = nr1; i1 = ni1;
}

// gate on a pair of interleaved units (each unit = 2 complex: r0,i0,r1,i1)
__device__ __forceinline__ void gateU(float4& A, float4& B, float c, float s)
{
    gate1(A.x, A.y, B.x, B.y, c, s);
    gate1(A.z, A.w, B.z, B.w, c, s);
}

// gate across two (R,I) float4 pairs, componentwise (4 complex each side)
__device__ __forceinline__ void gateV(float4& Ra, float4& Ia, float4& Rb, float4& Ib,
                                      float c, float s)
{
    gate1(Ra.x, Ia.x, Rb.x, Ib.x, c, s);
    gate1(Ra.y, Ia.y, Rb.y, Ib.y, c, s);
    gate1(Ra.z, Ia.z, Rb.z, Ib.z, c, s);
    gate1(Ra.w, Ia.w, Rb.w, Ib.w, c, s);
}

// per-CTA coefficient table: sc[a]=cos(angle[a]/2), ss[a]=sin(angle[a]/2).
// Complex bit b uses angle index 21-b.
#define MAKE_COEFS(ang, sc, ss, t)                                            \
    do {                                                                      \
        if ((t) < 22) {                                                       \
            float c_, s_;                                                     \
            sincosf(0.5f * __ldg((ang) + (t)), &s_, &c_);                     \
            (sc)[t] = c_; (ss)[t] = s_;                                       \
        }                                                                     \
    } while (0)

// ---------------------------------------------------------------------------
// Kernel A: gates on complex bits 0..12 (angles 21..9).
// Tile = 8192 contiguous complex (64KB smem, 4096 units). 512 threads.
// Phases: fill(bits 0-3) |h| R2(4-6) |h| R3(7-9) |F| drain(10-12)+store.
// |h| = half-CTA barrier (exchange is half-local), |F| = full barrier.
// ---------------------------------------------------------------------------
__global__ void __launch_bounds__(512, 2) gateA(const float* __restrict__ xr,
                                                const float* __restrict__ xi,
                                                const float* __restrict__ ang,
                                                float* __restrict__ outr,
                                                float* __restrict__ outi)
{
    extern __shared__ float4 sm[];            // 4096 units = 64KB
    __shared__ float sc[22], ss[22];
    const int t = threadIdx.x;
    const unsigned base = (unsigned)blockIdx.x << 13;

    MAKE_COEFS(ang, sc, ss, t);

    // ---- fill: 16 contiguous complex/thread, gate bits 0..3 ----
    {
        float4 R[4], I[4];
        const float4* pr = reinterpret_cast<const float4*>(xr + base) + t * 4;
        const float4* pi = reinterpret_cast<const float4*>(xi + base) + t * 4;
#pragma unroll
        for (int q = 0; q < 4; ++q) { R[q] = pr[q]; I[q] = pi[q]; }

        __syncthreads();                      // coefs ready (after LDG issue)

        float c0 = sc[21], s0 = ss[21], c1 = sc[20], s1 = ss[20];
        float c2 = sc[19], s2 = ss[19], c3 = sc[18], s3 = ss[18];
#pragma unroll
        for (int q = 0; q < 4; ++q) {         // bit 0
            gate1(R[q].x, I[q].x, R[q].y, I[q].y, c0, s0);
            gate1(R[q].z, I[q].z, R[q].w, I[q].w, c0, s0);
        }
#pragma unroll
        for (int q = 0; q < 4; ++q) {         // bit 1
            gate1(R[q].x, I[q].x, R[q].z, I[q].z, c1, s1);
            gate1(R[q].y, I[q].y, R[q].w, I[q].w, c1, s1);
        }
        gateV(R[0], I[0], R[1], I[1], c2, s2);   // bit 2
        gateV(R[2], I[2], R[3], I[3], c2, s2);
        gateV(R[0], I[0], R[2], I[2], c3, s3);   // bit 3
        gateV(R[1], I[1], R[3], I[3], c3, s3);

#pragma unroll
        for (int m = 0; m < 8; ++m) {
            int q = m >> 1;
            float4 u = (m & 1) ? make_float4(R[q].z, I[q].z, R[q].w, I[q].w)
                               : make_float4(R[q].x, I[q].x, R[q].y, I[q].y);
            sm[SW(t * 8 + m)] = u;
        }
    }
    BAR_HALF(t);

    float4 U[8];

    // ---- R2: gates bits 4-6 (unit bits 3-5), angles 17,16,15 ----
    {
        const int lo = t & 7, hi = t >> 3;
#pragma unroll
        for (int j = 0; j < 8; ++j) U[j] = sm[SW((hi << 6) | (j << 3) | lo)];
        float c0 = sc[17], s0 = ss[17], c1 = sc[16], s1 = ss[16];
        float c2 = sc[15], s2 = ss[15];
#pragma unroll
        for (int p = 0; p < 8; ++p) if (!(p & 1)) gateU(U[p], U[p | 1], c0, s0);
#pragma unroll
        for (int p = 0; p < 8; ++p) if (!(p & 2)) gateU(U[p], U[p | 2], c1, s1);
#pragma unroll
        for (int p = 0; p < 8; ++p) if (!(p & 4)) gateU(U[p], U[p | 4], c2, s2);
#pragma unroll
        for (int j = 0; j < 8; ++j) sm[SW((hi << 6) | (j << 3) | lo)] = U[j];
    }
    BAR_HALF(t);

    // ---- R3: gates bits 7-9 (unit bits 6-8), angles 14,13,12 ----
    {
        const int lo = t & 63, hi = t >> 6;
#pragma unroll
        for (int j = 0; j < 8; ++j) U[j] = sm[SW((hi << 9) | (j << 6) | lo)];
        float c0 = sc[14], s0 = ss[14], c1 = sc[13], s1 = ss[13];
        float c2 = sc[12], s2 = ss[12];
#pragma unroll
        for (int p = 0; p < 8; ++p) if (!(p & 1)) gateU(U[p], U[p | 1], c0, s0);
#pragma unroll
        for (int p = 0; p < 8; ++p) if (!(p & 2)) gateU(U[p], U[p | 2], c1, s1);
#pragma unroll
        for (int p = 0; p < 8; ++p) if (!(p & 4)) gateU(U[p], U[p | 4], c2, s2);
#pragma unroll
        for (int j = 0; j < 8; ++j) sm[SW((hi << 9) | (j << 6) | lo)] = U[j];
    }
    __syncthreads();                          // drain crosses CTA halves

    // ---- drain: gates bits 10-12 (unit bits 9-11), angles 11,10,9; store ----
    {
#pragma unroll
        for (int j = 0; j < 8; ++j) U[j] = sm[SW((j << 9) | t)];
        float c0 = sc[11], s0 = ss[11], c1 = sc[10], s1 = ss[10];
        float c2 = sc[9],  s2 = ss[9];
#pragma unroll
        for (int p = 0; p < 8; ++p) if (!(p & 1)) gateU(U[p], U[p | 1], c0, s0);
#pragma unroll
        for (int p = 0; p < 8; ++p) if (!(p & 2)) gateU(U[p], U[p | 2], c1, s1);
#pragma unroll
        for (int p = 0; p < 8; ++p) if (!(p & 4)) gateU(U[p], U[p | 4], c2, s2);
#pragma unroll
        for (int j = 0; j < 8; ++j) {
            unsigned c = base + ((unsigned)j << 10) + 2u * (unsigned)t;
            float4 A = U[j];
            *reinterpret_cast<float2*>(outr + c) = make_float2(A.x, A.z);
            *reinterpret_cast<float2*>(outi + c) = make_float2(A.y, A.w);
        }
    }
}

// ---------------------------------------------------------------------------
// Kernel B: gates on complex bits 13..21 (angles 8..0). In-place on out.
// Tile = 16 contiguous (bits 0-3, passive) x 512 strided h (bits 13-21).
// 512 threads, 64KB dyn smem, 4096 units; unit u = (h<<3)|(uq<<1)|ulo holds
// complex (h, lo = 4*uq + 2*ulo + {0,1}) as r,i,r,i.  64B/h/plane global rows
// -> 8 lines per warp global op (vs 16 before).
// Phases: fill+gates(h7,h8) |F| h0-2 |h| h3-5 |h| drain+gate(h6)+store.
// ---------------------------------------------------------------------------
__global__ void __launch_bounds__(512, 2) gateB(float* __restrict__ dr,
                                                float* __restrict__ di,
                                                const float* __restrict__ ang)
{
    extern __shared__ float4 sm[];            // 4096 units = 64KB
    __shared__ float sc[22], ss[22];
    const int t = threadIdx.x;
    const unsigned base = (unsigned)blockIdx.x << 4;   // k bits 4-12

    MAKE_COEFS(ang, sc, ss, t);

    float4 U[8];

    // ---- fill + gates h7 (bit 20, angle 1), h8 (bit 21, angle 0) ----
    {
        const int uq = t & 3;                 // which float4 of the 64B row
        const int hm = t >> 2;                // h bits 0..6
#pragma unroll
        for (int j = 0; j < 4; ++j) {         // j = (h8<<1)|h7
            unsigned h = ((unsigned)j << 7) | (unsigned)hm;
            unsigned g = (h << 13) + base + 4u * (unsigned)uq;
            float4 R = *reinterpret_cast<const float4*>(dr + g);
            float4 I = *reinterpret_cast<const float4*>(di + g);
            U[2 * j]     = make_float4(R.x, I.x, R.y, I.y);
            U[2 * j + 1] = make_float4(R.z, I.z, R.w, I.w);
        }
        __syncthreads();                      // coefs ready (after LDG issue)
        float c0 = sc[1], s0 = ss[1], c1 = sc[0], s1 = ss[0];
#pragma unroll
        for (int p = 0; p < 8; ++p) if (!(p & 2)) gateU(U[p], U[p | 2], c0, s0);
#pragma unroll
        for (int p = 0; p < 8; ++p) if (!(p & 4)) gateU(U[p], U[p | 4], c1, s1);
#pragma unroll
        for (int j = 0; j < 4; ++j)
#pragma unroll
            for (int ulo = 0; ulo < 2; ++ulo)
                sm[SW((j << 10) | (hm << 3) | (uq << 1) | ulo)] = U[2 * j + ulo];
    }
    __syncthreads();                          // fill writes cross CTA halves

    // ---- Rd1: gates h0,h1,h2 (bits 13-15, angles 8,7,6) ----
    {
        const int ul = t & 7, hp = t >> 3;    // hp = h bits 3..8
#pragma unroll
        for (int j = 0; j < 8; ++j) U[j] = sm[SW((hp << 6) | (j << 3) | ul)];
        float c0 = sc[8], s0 = ss[8], c1 = sc[7], s1 = ss[7];
        float c2 = sc[6], s2 = ss[6];
#pragma unroll
        for (int p = 0; p < 8; ++p) if (!(p & 1)) gateU(U[p], U[p | 1], c0, s0);
#pragma unroll
        for (int p = 0; p < 8; ++p) if (!(p & 2)) gateU(U[p], U[p | 2], c1, s1);
#pragma unroll
        for (int p = 0; p < 8; ++p) if (!(p & 4)) gateU(U[p], U[p | 4], c2, s2);
#pragma unroll
        for (int j = 0; j < 8; ++j) sm[SW((hp << 6) | (j << 3) | ul)] = U[j];
    }
    BAR_HALF(t);

    // ---- Rd2: gates h3,h4,h5 (bits 16-18, angles 5,4,3) ----
    {
        const int ul = t & 7, hl = (t >> 3) & 7, ht = t >> 6;  // ht = h bits 6-8
#pragma unroll
        for (int j = 0; j < 8; ++j)
            U[j] = sm[SW((ht << 9) | (j << 6) | (hl << 3) | ul)];
        float c0 = sc[5], s0 = ss[5], c1 = sc[4], s1 = ss[4];
        float c2 = sc[3], s2 = ss[3];
#pragma unroll
        for (int p = 0; p < 8; ++p) if (!(p & 1)) gateU(U[p], U[p | 1], c0, s0);
#pragma unroll
        for (int p = 0; p < 8; ++p) if (!(p & 2)) gateU(U[p], U[p | 2], c1, s1);
#pragma unroll
        for (int p = 0; p < 8; ++p) if (!(p & 4)) gateU(U[p], U[p | 4], c2, s2);
#pragma unroll
        for (int j = 0; j < 8; ++j)
            sm[SW((ht << 9) | (j << 6) | (hl << 3) | ul)] = U[j];
    }
    BAR_HALF(t);

    // ---- drain: gate h6 (bit 19, angle 2); 64B-row coalesced store ----
    {
        const int uq = t & 3;
        const int hlow = (t >> 2) & 63;       // h bits 0..5
        const int h8 = t >> 8;                // h bit 8
#pragma unroll
        for (int j = 0; j < 4; ++j) {         // j = (h7<<1)|h6
            int h = (h8 << 8) | (j << 6) | hlow;
#pragma unroll
            for (int ulo = 0; ulo < 2; ++ulo)
                U[2 * j + ulo] = sm[SW((h << 3) | (uq << 1) | ulo)];
        }
        float c0 = sc[2], s0 = ss[2];
#pragma unroll
        for (int p = 0; p < 8; ++p) if (!(p & 2)) gateU(U[p], U[p | 2], c0, s0);
#pragma unroll
        for (int j = 0; j < 4; ++j) {
            unsigned h = ((unsigned)h8 << 8) | ((unsigned)j << 6) | (unsigned)hlow;
            unsigned g = (h << 13) + base + 4u * (unsigned)uq;
            float4 A = U[2 * j], B = U[2 * j + 1];
            *reinterpret_cast<float4*>(dr + g) = make_float4(A.x, A.z, B.x, B.z);
            *reinterpret_cast<float4*>(di + g) = make_float4(A.y, A.w, B.y, B.w);
        }
    }
}

extern "C" void kernel_launch(void* const* d_in, const int* in_sizes, int n_in,
                              void* d_out, int out_size)
{
    const float* xr  = (const float*)d_in[0];
    const float* xi  = (const float*)d_in[1];
    const float* ang = (const float*)d_in[2];
    float* outr = (float*)d_out;
    float* outi = outr + NSTATE;

    const int sh = 4096 * sizeof(float4);     // 64KB
    cudaFuncSetAttribute(gateA, cudaFuncAttributeMaxDynamicSharedMemorySize, sh);
    cudaFuncSetAttribute(gateB, cudaFuncAttributeMaxDynamicSharedMemorySize, sh);

    // Pass 1: gates on bits 0..12 (input -> out)
    gateA<<<NSTATE / 8192, 512, sh>>>(xr, xi, ang, outr, outi);

    // Pass 2: gates on bits 13..21 (in-place on out)
    gateB<<<NSTATE / 8192, 512, sh>>>(outr, outi, ang);
}